// round 11
// baseline (speedup 1.0000x reference)
#include <cuda_runtime.h>
#include <cuda_bf16.h>
#include <math.h>
#include <stdint.h>

#define DIM   768
#define HEADS 12
#define HD    64
#define BS    32
#define NMM   256
#define NV    196
#define NA    60
#define NKV   256
#define M_ROWS (BS * NMM)       // 8192

// ---------------- scratch (device globals; no cudaMalloc allowed) ----------
__device__ __align__(16) __nv_bfloat16 g_Qh[BS * HEADS * NMM * HD];  // [b,h,q,d] (pre-scaled)
__device__ __align__(16) __nv_bfloat16 g_Ql[BS * HEADS * NMM * HD];
__device__ __align__(16) __nv_bfloat16 g_Kh[BS * HEADS * NKV * HD];  // [b,h,k,d]
__device__ __align__(16) __nv_bfloat16 g_Kl[BS * HEADS * NKV * HD];
__device__ __align__(16) __nv_bfloat16 g_VTh[BS * HEADS * HD * NKV]; // [b,h,d,k]
__device__ __align__(16) __nv_bfloat16 g_VTl[BS * HEADS * HD * NKV];

__device__ __align__(16) __nv_bfloat16 g_Amm_hi [M_ROWS * DIM];
__device__ __align__(16) __nv_bfloat16 g_Amm_lo [M_ROWS * DIM];
__device__ __align__(16) __nv_bfloat16 g_Asrc_hi[M_ROWS * DIM];
__device__ __align__(16) __nv_bfloat16 g_Asrc_lo[M_ROWS * DIM];
__device__ __align__(16) __nv_bfloat16 g_AO_hi  [M_ROWS * DIM];
__device__ __align__(16) __nv_bfloat16 g_AO_lo  [M_ROWS * DIM];
__device__ __align__(16) __nv_bfloat16 g_WqT_hi [DIM * DIM];      // [n][k]
__device__ __align__(16) __nv_bfloat16 g_WqT_lo [DIM * DIM];
__device__ __align__(16) __nv_bfloat16 g_WkvT_hi[2 * DIM * DIM];
__device__ __align__(16) __nv_bfloat16 g_WkvT_lo[2 * DIM * DIM];
__device__ __align__(16) __nv_bfloat16 g_WpT_hi [DIM * DIM];
__device__ __align__(16) __nv_bfloat16 g_WpT_lo [DIM * DIM];

// ---------------- PTX helpers (plain-sm_103-legal) -------------------------
__device__ __forceinline__ uint32_t smem_u32(const void* p) {
    uint32_t a;
    asm("{ .reg .u64 t; cvta.to.shared.u64 t, %1; cvt.u32.u64 %0, t; }" : "=r"(a) : "l"(p));
    return a;
}
__device__ __forceinline__ void cp_async16(uint32_t dst, const void* src) {
    asm volatile("cp.async.cg.shared.global [%0], [%1], 16;" :: "r"(dst), "l"(src));
}
__device__ __forceinline__ void cp_commit() {
    asm volatile("cp.async.commit_group;" ::: "memory");
}
template <int N>
__device__ __forceinline__ void cp_wait() {
    asm volatile("cp.async.wait_group %0;" :: "n"(N) : "memory");
}
__device__ __forceinline__ void ldmatrix_x4(uint32_t& r0, uint32_t& r1, uint32_t& r2,
                                            uint32_t& r3, uint32_t addr) {
    asm volatile("ldmatrix.sync.aligned.m8n8.x4.shared.b16 {%0,%1,%2,%3}, [%4];"
                 : "=r"(r0), "=r"(r1), "=r"(r2), "=r"(r3) : "r"(addr));
}
__device__ __forceinline__ void mma_bf16(float* c, const uint32_t* a, const uint32_t* b) {
    asm volatile(
        "mma.sync.aligned.m16n8k16.row.col.f32.bf16.bf16.f32 "
        "{%0,%1,%2,%3}, {%4,%5,%6,%7}, {%8,%9}, {%0,%1,%2,%3};"
        : "+f"(c[0]), "+f"(c[1]), "+f"(c[2]), "+f"(c[3])
        : "r"(a[0]), "r"(a[1]), "r"(a[2]), "r"(a[3]), "r"(b[0]), "r"(b[1]));
}
__device__ __forceinline__ void bfsplit(float x, __nv_bfloat16& hi, __nv_bfloat16& lo) {
    hi = __float2bfloat16(x);
    lo = __float2bfloat16(x - __bfloat162float(hi));
}

// ---------------- prep kernels ---------------------------------------------
__global__ void k_split(const float* __restrict__ s) {      // xmm -> g_Amm
    const int i = blockIdx.x * 256 + threadIdx.x;
    if (i >= M_ROWS * DIM / 2) return;
    const float2 v = reinterpret_cast<const float2*>(s)[i];
    __nv_bfloat16 h0, l0, h1, l1;
    bfsplit(v.x, h0, l0); bfsplit(v.y, h1, l1);
    reinterpret_cast<__nv_bfloat162*>(g_Amm_hi)[i] = __halves2bfloat162(h0, h1);
    reinterpret_cast<__nv_bfloat162*>(g_Amm_lo)[i] = __halves2bfloat162(l0, l1);
}

__global__ void k_split_gather(const float* __restrict__ xv, const float* __restrict__ xa) {
    const int u = blockIdx.x * 256 + threadIdx.x;
    if (u >= M_ROWS * DIM / 2) return;
    const int row = u / (DIM / 2), c2 = u - row * (DIM / 2);
    const int b = row >> 8, t = row & 255;
    const float* src = (t < NV) ? xv + ((size_t)(b * NV + t)) * DIM
                                : xa + ((size_t)(b * NA + (t - NV))) * DIM;
    const float2 v = reinterpret_cast<const float2*>(src)[c2];
    __nv_bfloat16 h0, l0, h1, l1;
    bfsplit(v.x, h0, l0); bfsplit(v.y, h1, l1);
    reinterpret_cast<__nv_bfloat162*>(g_Asrc_hi)[u] = __halves2bfloat162(h0, h1);
    reinterpret_cast<__nv_bfloat162*>(g_Asrc_lo)[u] = __halves2bfloat162(l0, l1);
}

template <int WSEL>   // 0=Wq, 1=Wkv, 2=Wproj  : W [768][N] -> WT hi/lo [N][768]
__global__ void k_transpose_split(const float* __restrict__ W, int N) {
    __shared__ float t[32][33];
    const int n0 = blockIdx.x * 32, k0 = blockIdx.y * 32;
    const int tx = threadIdx.x & 31, ty = threadIdx.x >> 5;   // 32 x 8
#pragma unroll
    for (int i = 0; i < 4; i++)
        t[ty + 8 * i][tx] = W[(size_t)(k0 + ty + 8 * i) * N + n0 + tx];
    __syncthreads();
    __nv_bfloat16* Thi = (WSEL == 0) ? g_WqT_hi : (WSEL == 1) ? g_WkvT_hi : g_WpT_hi;
    __nv_bfloat16* Tlo = (WSEL == 0) ? g_WqT_lo : (WSEL == 1) ? g_WkvT_lo : g_WpT_lo;
#pragma unroll
    for (int i = 0; i < 4; i++) {
        const float x = t[tx][ty + 8 * i];
        __nv_bfloat16 h, l;
        bfsplit(x, h, l);
        const size_t o = (size_t)(n0 + ty + 8 * i) * DIM + k0 + tx;
        Thi[o] = h; Tlo[o] = l;
    }
}

// ---------------- projection GEMMs (mma.sync, bf16 hi/lo) ------------------
// CTA tile 128(M) x 256(N), BK=32. 8 warps as 2(m) x 4(n), warp tile 64x64.
#define A_TB   8192                 // A tile: 128 x 32 bf16
#define B_TB   16384                // B tile: 256 x 32 bf16
#define STG_B  (2 * A_TB + 2 * B_TB)   // 49152 per stage
__device__ __forceinline__ uint32_t sw_off(int row, int c16) {
    return (uint32_t)(row * 64 + ((c16 ^ ((row >> 1) & 3)) << 4));
}

template <int MODE>   // 0: Q-proj, 1: KV-proj, 2: O-proj
__global__ __launch_bounds__(256, 1)
void tc_gemm(const float* __restrict__ bias, float* __restrict__ C)
{
    extern __shared__ char smem[];
    const uint32_t sb = smem_u32(smem);
    const int tid = threadIdx.x, wid = tid >> 5, lane = tid & 31;
    const int m0 = blockIdx.y * 128, n0 = blockIdx.x * 256;
    const int wm = wid & 1, wn = wid >> 1;

    const __nv_bfloat16* Ahi = (MODE == 0) ? g_Amm_hi : (MODE == 1) ? g_Asrc_hi : g_AO_hi;
    const __nv_bfloat16* Alo = (MODE == 0) ? g_Amm_lo : (MODE == 1) ? g_Asrc_lo : g_AO_lo;
    const __nv_bfloat16* Bhi = (MODE == 0) ? g_WqT_hi : (MODE == 1) ? g_WkvT_hi : g_WpT_hi;
    const __nv_bfloat16* Blo = (MODE == 0) ? g_WqT_lo : (MODE == 1) ? g_WkvT_lo : g_WpT_lo;

    const char* gAh = (const char*)(Ahi + (size_t)m0 * DIM);
    const char* gAl = (const char*)(Alo + (size_t)m0 * DIM);
    const char* gBh = (const char*)(Bhi + (size_t)n0 * DIM);
    const char* gBl = (const char*)(Blo + (size_t)n0 * DIM);

    auto issue = [&](int it) {
        const int kb = it * 64;
        const uint32_t bufb = sb + (uint32_t)(it & 1) * STG_B;
#pragma unroll
        for (int u = 0; u < 2; u++) {                 // A hi/lo: 512 chunks each
            const int i = u * 256 + tid;
            const int row = i >> 2, c16 = i & 3;
            const uint32_t o = sw_off(row, c16);
            cp_async16(bufb + o,        gAh + (size_t)row * (DIM * 2) + kb + c16 * 16);
            cp_async16(bufb + A_TB + o, gAl + (size_t)row * (DIM * 2) + kb + c16 * 16);
        }
#pragma unroll
        for (int u = 0; u < 4; u++) {                 // B hi/lo: 1024 chunks each
            const int i = u * 256 + tid;
            const int row = i >> 2, c16 = i & 3;
            const uint32_t o = sw_off(row, c16);
            cp_async16(bufb + 2 * A_TB + o,        gBh + (size_t)row * (DIM * 2) + kb + c16 * 16);
            cp_async16(bufb + 2 * A_TB + B_TB + o, gBl + (size_t)row * (DIM * 2) + kb + c16 * 16);
        }
        cp_commit();
    };

    float acc[4][8][4];
#pragma unroll
    for (int i = 0; i < 4; i++)
#pragma unroll
        for (int j = 0; j < 8; j++)
#pragma unroll
            for (int r = 0; r < 4; r++) acc[i][j][r] = 0.f;

    const int matA = lane >> 3, wiA = lane & 7;
    const int a_moff = ((matA & 1) << 3) + wiA;
    const int a_ksel = matA >> 1;
    const int b_noff = ((matA >> 1) << 3) + wiA;
    const int b_ksel = matA & 1;

    issue(0);
    const int NITER = DIM / 32;                        // 24
    for (int it = 0; it < NITER; it++) {
        if (it + 1 < NITER) { issue(it + 1); cp_wait<1>(); }
        else                 cp_wait<0>();
        __syncthreads();
        const uint32_t bufb = sb + (uint32_t)(it & 1) * STG_B;
        const uint32_t sAh = bufb, sAl = bufb + A_TB;
        const uint32_t sBh = bufb + 2 * A_TB, sBl = bufb + 2 * A_TB + B_TB;
#pragma unroll
        for (int kk = 0; kk < 2; kk++) {
            uint32_t ah[4][4], al[4][4];
#pragma unroll
            for (int mi = 0; mi < 4; mi++) {
                const int row = wm * 64 + mi * 16 + a_moff;
                const uint32_t o = sw_off(row, kk * 2 + a_ksel);
                ldmatrix_x4(ah[mi][0], ah[mi][1], ah[mi][2], ah[mi][3], sAh + o);
                ldmatrix_x4(al[mi][0], al[mi][1], al[mi][2], al[mi][3], sAl + o);
            }
#pragma unroll
            for (int ni = 0; ni < 4; ni++) {
                uint32_t bh[4], bl[4];
                const int row = wn * 64 + ni * 16 + b_noff;
                const uint32_t o = sw_off(row, kk * 2 + b_ksel);
                ldmatrix_x4(bh[0], bh[1], bh[2], bh[3], sBh + o);
                ldmatrix_x4(bl[0], bl[1], bl[2], bl[3], sBl + o);
#pragma unroll
                for (int mi = 0; mi < 4; mi++)
#pragma unroll
                    for (int n8 = 0; n8 < 2; n8++) {
                        const int p = n8 << 1;
                        uint32_t bfh[2] = { bh[p], bh[p + 1] };
                        uint32_t bfl[2] = { bl[p], bl[p + 1] };
                        float* a = acc[mi][ni * 2 + n8];
                        mma_bf16(a, ah[mi], bfh);
                        mma_bf16(a, ah[mi], bfl);
                        mma_bf16(a, al[mi], bfh);
                    }
            }
        }
        __syncthreads();
    }

    const int gi = lane >> 2, qi = lane & 3;
#pragma unroll
    for (int mi = 0; mi < 4; mi++)
#pragma unroll
        for (int j = 0; j < 8; j++)
#pragma unroll
            for (int half = 0; half < 2; half++) {
                const int r  = m0 + wm * 64 + mi * 16 + gi + half * 8;
                const int cg = n0 + wn * 64 + (j >> 1) * 16 + (j & 1) * 8 + qi * 2;
                float2 v = make_float2(acc[mi][j][2 * half], acc[mi][j][2 * half + 1]);
                if (MODE == 0) {
                    v.x *= 0.125f; v.y *= 0.125f;          // fold 1/sqrt(hd), exact
                    const int b = r >> 8, q = r & 255, h = cg >> 6, d = cg & 63;
                    __nv_bfloat16 hx, lx, hy, ly;
                    bfsplit(v.x, hx, lx); bfsplit(v.y, hy, ly);
                    const size_t o = (((size_t)b * HEADS + h) * NMM + q) * HD + d;
                    *reinterpret_cast<__nv_bfloat162*>(&g_Qh[o]) = __halves2bfloat162(hx, hy);
                    *reinterpret_cast<__nv_bfloat162*>(&g_Ql[o]) = __halves2bfloat162(lx, ly);
                } else if (MODE == 1) {
                    const int b = r >> 8, t = r & 255;
                    __nv_bfloat16 hx, lx, hy, ly;
                    bfsplit(v.x, hx, lx); bfsplit(v.y, hy, ly);
                    if (cg < DIM) {
                        const int h = cg >> 6, d = cg & 63;
                        const size_t o = (((size_t)b * HEADS + h) * NKV + t) * HD + d;
                        *reinterpret_cast<__nv_bfloat162*>(&g_Kh[o]) = __halves2bfloat162(hx, hy);
                        *reinterpret_cast<__nv_bfloat162*>(&g_Kl[o]) = __halves2bfloat162(lx, ly);
                    } else {
                        const int c2 = cg - DIM, h = c2 >> 6, d = c2 & 63;
                        const size_t vb = ((size_t)b * HEADS + h) * HD;
                        g_VTh[(vb + d) * NKV + t] = hx; g_VTh[(vb + d + 1) * NKV + t] = hy;
                        g_VTl[(vb + d) * NKV + t] = lx; g_VTl[(vb + d + 1) * NKV + t] = ly;
                    }
                } else {
                    v.x += bias[cg]; v.y += bias[cg + 1];
                    *reinterpret_cast<float2*>(&C[(size_t)r * DIM + cg]) = v;
                }
            }
}

// ---------------- fused attention (unchanged from R8) ----------------------
#define FA_KB   0
#define FA_QB   65536
#define FA_VB   81920
#define FA_RED  147456
#define FA_SMEM (FA_RED + 2048)

__global__ __launch_bounds__(256, 1)
void fattn(float* __restrict__ attn)
{
    extern __shared__ char smem[];
    const uint32_t sb = smem_u32(smem);
    const int tid = threadIdx.x, wid = tid >> 5, lane = tid & 31;
    const int m0 = blockIdx.x * 64, bh = blockIdx.y;
    const int b = bh / HEADS, h = bh - b * HEADS;
    const int wm = wid & 1, wn = wid >> 1;            // S phase: 2(m) x 4(n)

    const int matA = lane >> 3, wiA = lane & 7;
    const int a_moff = ((matA & 1) << 3) + wiA;
    const int a_ksel = matA >> 1;
    const int b_noff = ((matA >> 1) << 3) + wiA;
    const int b_ksel = matA & 1;
    const int gi = lane >> 2, qi = lane & 3;

    const char* KH = (const char*)(g_Kh + (size_t)bh * NKV * HD);
    const char* KL = (const char*)(g_Kl + (size_t)bh * NKV * HD);
    const char* QH = (const char*)(g_Qh + ((size_t)bh * NMM + m0) * HD);
    const char* QL = (const char*)(g_Ql + ((size_t)bh * NMM + m0) * HD);
    const char* VH = (const char*)(g_VTh + (size_t)bh * HD * NKV);
    const char* VL = (const char*)(g_VTl + (size_t)bh * HD * NKV);

#pragma unroll
    for (int u = 0; u < 8; u++) {
        const int i = u * 256 + tid;
        const int t = i >> 3, c = (i >> 2) & 1, c16 = i & 3;
        cp_async16(sb + FA_KB + c * 16384 + sw_off(t, c16), KH + t * 128 + c * 64 + c16 * 16);
        cp_async16(sb + FA_KB + 32768 + c * 16384 + sw_off(t, c16), KL + t * 128 + c * 64 + c16 * 16);
    }
#pragma unroll
    for (int u = 0; u < 2; u++) {
        const int i = u * 256 + tid;
        const int r = i >> 3, c = (i >> 2) & 1, c16 = i & 3;
        cp_async16(sb + FA_QB + c * 4096 + sw_off(r, c16), QH + r * 128 + c * 64 + c16 * 16);
        cp_async16(sb + FA_QB + 8192 + c * 4096 + sw_off(r, c16), QL + r * 128 + c * 64 + c16 * 16);
    }
    cp_commit();
#pragma unroll
    for (int u = 0; u < 8; u++) {
        const int i = u * 256 + tid;
        const int d = i >> 5, ch = (i >> 2) & 7, c16 = i & 3;
        cp_async16(sb + FA_VB + ch * 4096 + sw_off(d, c16), VH + d * 512 + ch * 64 + c16 * 16);
        cp_async16(sb + FA_VB + 32768 + ch * 4096 + sw_off(d, c16), VL + d * 512 + ch * 64 + c16 * 16);
    }
    cp_commit();
    cp_wait<1>();
    __syncthreads();

    float acc[2][8][4];
#pragma unroll
    for (int i = 0; i < 2; i++)
#pragma unroll
        for (int j = 0; j < 8; j++)
#pragma unroll
            for (int r = 0; r < 4; r++) acc[i][j][r] = 0.f;

#pragma unroll
    for (int ch = 0; ch < 2; ch++)
#pragma unroll
        for (int kk = 0; kk < 2; kk++) {
            uint32_t ah[2][4], al[2][4], bhv[4][4], blv[4][4];
#pragma unroll
            for (int mi = 0; mi < 2; mi++) {
                const int row = wm * 32 + mi * 16 + a_moff;
                const uint32_t o = FA_QB + ch * 4096 + sw_off(row, kk * 2 + a_ksel);
                ldmatrix_x4(ah[mi][0], ah[mi][1], ah[mi][2], ah[mi][3], sb + o);
                ldmatrix_x4(al[mi][0], al[mi][1], al[mi][2], al[mi][3], sb + o + 8192);
            }
#pragma unroll
            for (int ni = 0; ni < 4; ni++) {
                const int row = wn * 64 + ni * 16 + b_noff;
                const uint32_t o = FA_KB + ch * 16384 + sw_off(row, kk * 2 + b_ksel);
                ldmatrix_x4(bhv[ni][0], bhv[ni][1], bhv[ni][2], bhv[ni][3], sb + o);
                ldmatrix_x4(blv[ni][0], blv[ni][1], blv[ni][2], blv[ni][3], sb + o + 32768);
            }
#pragma unroll
            for (int mi = 0; mi < 2; mi++)
#pragma unroll
                for (int n8 = 0; n8 < 8; n8++) {
                    const int ni = n8 >> 1, p = (n8 & 1) << 1;
                    uint32_t bfh[2] = { bhv[ni][p], bhv[ni][p + 1] };
                    uint32_t bfl[2] = { blv[ni][p], blv[ni][p + 1] };
                    mma_bf16(acc[mi][n8], ah[mi], bfh);
                    mma_bf16(acc[mi][n8], ah[mi], bfl);
                    mma_bf16(acc[mi][n8], al[mi], bfh);
                }
        }
    __syncthreads();

    float* redm = (float*)(smem + FA_RED);
    float* reds = (float*)(smem + FA_RED + 1024);
    float inv[2][2];
#pragma unroll
    for (int mi = 0; mi < 2; mi++)
#pragma unroll
        for (int hf = 0; hf < 2; hf++) {
            float m = -INFINITY;
#pragma unroll
            for (int n8 = 0; n8 < 8; n8++)
                m = fmaxf(m, fmaxf(acc[mi][n8][2 * hf], acc[mi][n8][2 * hf + 1]));
            m = fmaxf(m, __shfl_xor_sync(0xFFFFFFFFu, m, 1));
            m = fmaxf(m, __shfl_xor_sync(0xFFFFFFFFu, m, 2));
            if (qi == 0) redm[wn * 64 + wm * 32 + mi * 16 + gi + hf * 8] = m;
        }
    __syncthreads();
#pragma unroll
    for (int mi = 0; mi < 2; mi++)
#pragma unroll
        for (int hf = 0; hf < 2; hf++) {
            const int rl = wm * 32 + mi * 16 + gi + hf * 8;
            float m = fmaxf(fmaxf(redm[rl], redm[64 + rl]),
                            fmaxf(redm[128 + rl], redm[192 + rl]));
            float s = 0.f;
#pragma unroll
            for (int n8 = 0; n8 < 8; n8++) {
                float e0 = __expf(acc[mi][n8][2 * hf] - m);
                float e1 = __expf(acc[mi][n8][2 * hf + 1] - m);
                acc[mi][n8][2 * hf] = e0; acc[mi][n8][2 * hf + 1] = e1;
                s += e0 + e1;
            }
            s += __shfl_xor_sync(0xFFFFFFFFu, s, 1);
            s += __shfl_xor_sync(0xFFFFFFFFu, s, 2);
            if (qi == 0) reds[wn * 64 + rl] = s;
        }
    __syncthreads();
#pragma unroll
    for (int mi = 0; mi < 2; mi++)
#pragma unroll
        for (int hf = 0; hf < 2; hf++) {
            const int rl = wm * 32 + mi * 16 + gi + hf * 8;
            inv[mi][hf] = 1.0f / (reds[rl] + reds[64 + rl] + reds[128 + rl] + reds[192 + rl]);
        }

    float* outp = attn + ((size_t)bh * NMM + m0) * NKV;
#pragma unroll
    for (int mi = 0; mi < 2; mi++)
#pragma unroll
        for (int n8 = 0; n8 < 8; n8++)
#pragma unroll
            for (int hf = 0; hf < 2; hf++) {
                const int rl = wm * 32 + mi * 16 + gi + hf * 8;
                const int col = wn * 64 + n8 * 8 + qi * 2;
                const float px = acc[mi][n8][2 * hf] * inv[mi][hf];
                const float py = acc[mi][n8][2 * hf + 1] * inv[mi][hf];
                *reinterpret_cast<float2*>(&outp[(size_t)rl * NKV + col]) = make_float2(px, py);
                __nv_bfloat16 hx, lx, hy, ly;
                bfsplit(px, hx, lx); bfsplit(py, hy, ly);
                const int cc = col & 31;
                const uint32_t po = (uint32_t)((col >> 5) * 4096) + sw_off(rl, cc >> 3) + (cc & 7) * 2;
                __nv_bfloat162 hp = __halves2bfloat162(hx, hy);
                __nv_bfloat162 lp = __halves2bfloat162(lx, ly);
                *reinterpret_cast<uint32_t*>(smem + FA_KB + po) = *reinterpret_cast<uint32_t*>(&hp);
                *reinterpret_cast<uint32_t*>(smem + FA_KB + 32768 + po) = *reinterpret_cast<uint32_t*>(&lp);
            }
    cp_wait<0>();
    __syncthreads();

    const int om = wid & 3, on = wid >> 2;
    float oacc[4][4];
#pragma unroll
    for (int j = 0; j < 4; j++)
#pragma unroll
        for (int r = 0; r < 4; r++) oacc[j][r] = 0.f;

#pragma unroll
    for (int ch = 0; ch < 8; ch++)
#pragma unroll
        for (int kk = 0; kk < 2; kk++) {
            uint32_t pa[4], pl[4], vbh[2][4], vbl[2][4];
            {
                const int row = om * 16 + a_moff;
                const uint32_t o = FA_KB + ch * 4096 + sw_off(row, kk * 2 + a_ksel);
                ldmatrix_x4(pa[0], pa[1], pa[2], pa[3], sb + o);
                ldmatrix_x4(pl[0], pl[1], pl[2], pl[3], sb + o + 32768);
            }
#pragma unroll
            for (int ni = 0; ni < 2; ni++) {
                const int row = on * 32 + ni * 16 + b_noff;
                const uint32_t o = FA_VB + ch * 4096 + sw_off(row, kk * 2 + b_ksel);
                ldmatrix_x4(vbh[ni][0], vbh[ni][1], vbh[ni][2], vbh[ni][3], sb + o);
                ldmatrix_x4(vbl[ni][0], vbl[ni][1], vbl[ni][2], vbl[ni][3], sb + o + 32768);
            }
#pragma unroll
            for (int n8 = 0; n8 < 4; n8++) {
                const int ni = n8 >> 1, p = (n8 & 1) << 1;
                uint32_t bfh[2] = { vbh[ni][p], vbh[ni][p + 1] };
                uint32_t bfl[2] = { vbl[ni][p], vbl[ni][p + 1] };
                mma_bf16(oacc[n8], pa, bfh);
                mma_bf16(oacc[n8], pa, bfl);
                mma_bf16(oacc[n8], pl, bfh);
            }
        }

#pragma unroll
    for (int n8 = 0; n8 < 4; n8++)
#pragma unroll
        for (int hf = 0; hf < 2; hf++) {
            const int q = m0 + om * 16 + gi + hf * 8;
            const int d = on * 32 + n8 * 8 + qi * 2;
            __nv_bfloat16 hx, lx, hy, ly;
            bfsplit(oacc[n8][2 * hf], hx, lx); bfsplit(oacc[n8][2 * hf + 1], hy, ly);
            const size_t o = ((size_t)b * NMM + q) * DIM + h * HD + d;
            *reinterpret_cast<__nv_bfloat162*>(&g_AO_hi[o]) = __halves2bfloat162(hx, hy);
            *reinterpret_cast<__nv_bfloat162*>(&g_AO_lo[o]) = __halves2bfloat162(lx, ly);
        }
}

// ---------------------------------------------------------------------------
extern "C" void kernel_launch(void* const* d_in, const int* in_sizes, int n_in,
                              void* d_out, int out_size)
{
    const float* xmm   = (const float*)d_in[0];
    const float* xv    = (const float*)d_in[1];
    const float* xa    = (const float*)d_in[2];
    const float* Wq    = (const float*)d_in[3];
    const float* Wkv   = (const float*)d_in[4];
    const float* Wproj = (const float*)d_in[5];
    const float* bproj = (const float*)d_in[6];

    float* out  = (float*)d_out;
    float* attn = out + (size_t)BS * NMM * DIM;

    const int GEMM_SMEM = 2 * STG_B;   // 96 KB
    cudaFuncSetAttribute(tc_gemm<0>, cudaFuncAttributeMaxDynamicSharedMemorySize, GEMM_SMEM);
    cudaFuncSetAttribute(tc_gemm<1>, cudaFuncAttributeMaxDynamicSharedMemorySize, GEMM_SMEM);
    cudaFuncSetAttribute(tc_gemm<2>, cudaFuncAttributeMaxDynamicSharedMemorySize, GEMM_SMEM);
    cudaFuncSetAttribute(fattn,      cudaFuncAttributeMaxDynamicSharedMemorySize, FA_SMEM);

    const int nsplit = M_ROWS * DIM / 2;
    // Launch order puts tc_gemm<1> at index 3 (ncu's observed capture slot).
    k_split<<<(nsplit + 255) / 256, 256>>>(xmm);                               // 0
    k_split_gather<<<(nsplit + 255) / 256, 256>>>(xv, xa);                     // 1
    k_transpose_split<1><<<dim3(2 * DIM / 32, DIM / 32), 256>>>(Wkv, 2 * DIM); // 2
    tc_gemm<1><<<dim3(2 * DIM / 256, M_ROWS / 128), 256, GEMM_SMEM>>>(nullptr, nullptr); // 3
    k_transpose_split<0><<<dim3(DIM / 32, DIM / 32), 256>>>(Wq, DIM);          // 4
    tc_gemm<0><<<dim3(DIM / 256, M_ROWS / 128), 256, GEMM_SMEM>>>(nullptr, nullptr);     // 5
    fattn<<<dim3(NMM / 64, BS * HEADS), 256, FA_SMEM>>>(attn);                 // 6
    k_transpose_split<2><<<dim3(DIM / 32, DIM / 32), 256>>>(Wproj, DIM);       // 7
    tc_gemm<2><<<dim3(DIM / 256, M_ROWS / 128), 256, GEMM_SMEM>>>(bproj, out); // 8
}

// round 12
// speedup vs baseline: 1.1628x; 1.1628x over previous
#include <cuda_runtime.h>
#include <cuda_bf16.h>
#include <math.h>
#include <stdint.h>

#define DIM   768
#define HEADS 12
#define HD    64
#define BS    32
#define NMM   256
#define NV    196
#define NA    60
#define NKV   256
#define M_ROWS (BS * NMM)       // 8192

// ---------------- scratch (device globals; no cudaMalloc allowed) ----------
__device__ __align__(16) __nv_bfloat16 g_Qh[BS * HEADS * NMM * HD];  // [b,h,q,d] (pre-scaled)
__device__ __align__(16) __nv_bfloat16 g_Ql[BS * HEADS * NMM * HD];
__device__ __align__(16) __nv_bfloat16 g_Kh[BS * HEADS * NKV * HD];  // [b,h,k,d]
__device__ __align__(16) __nv_bfloat16 g_Kl[BS * HEADS * NKV * HD];
__device__ __align__(16) __nv_bfloat16 g_VTh[BS * HEADS * HD * NKV]; // [b,h,d,k]
__device__ __align__(16) __nv_bfloat16 g_VTl[BS * HEADS * HD * NKV];

__device__ __align__(16) __nv_bfloat16 g_Amm_hi [M_ROWS * DIM];
__device__ __align__(16) __nv_bfloat16 g_Amm_lo [M_ROWS * DIM];
__device__ __align__(16) __nv_bfloat16 g_Asrc_hi[M_ROWS * DIM];
__device__ __align__(16) __nv_bfloat16 g_Asrc_lo[M_ROWS * DIM];
__device__ __align__(16) __nv_bfloat16 g_AO_hi  [M_ROWS * DIM];
__device__ __align__(16) __nv_bfloat16 g_AO_lo  [M_ROWS * DIM];
__device__ __align__(16) __nv_bfloat16 g_WqT_hi [DIM * DIM];      // [n][k]
__device__ __align__(16) __nv_bfloat16 g_WqT_lo [DIM * DIM];
__device__ __align__(16) __nv_bfloat16 g_WkvT_hi[2 * DIM * DIM];
__device__ __align__(16) __nv_bfloat16 g_WkvT_lo[2 * DIM * DIM];
__device__ __align__(16) __nv_bfloat16 g_WpT_hi [DIM * DIM];
__device__ __align__(16) __nv_bfloat16 g_WpT_lo [DIM * DIM];

// ---------------- PTX helpers (plain-sm_103-legal) -------------------------
__device__ __forceinline__ uint32_t smem_u32(const void* p) {
    uint32_t a;
    asm("{ .reg .u64 t; cvta.to.shared.u64 t, %1; cvt.u32.u64 %0, t; }" : "=r"(a) : "l"(p));
    return a;
}
__device__ __forceinline__ void cp_async16(uint32_t dst, const void* src) {
    asm volatile("cp.async.cg.shared.global [%0], [%1], 16;" :: "r"(dst), "l"(src));
}
__device__ __forceinline__ void cp_commit() {
    asm volatile("cp.async.commit_group;" ::: "memory");
}
template <int N>
__device__ __forceinline__ void cp_wait() {
    asm volatile("cp.async.wait_group %0;" :: "n"(N) : "memory");
}
__device__ __forceinline__ void ldmatrix_x4(uint32_t& r0, uint32_t& r1, uint32_t& r2,
                                            uint32_t& r3, uint32_t addr) {
    asm volatile("ldmatrix.sync.aligned.m8n8.x4.shared.b16 {%0,%1,%2,%3}, [%4];"
                 : "=r"(r0), "=r"(r1), "=r"(r2), "=r"(r3) : "r"(addr));
}
__device__ __forceinline__ void mma_bf16(float* c, const uint32_t* a, const uint32_t* b) {
    asm volatile(
        "mma.sync.aligned.m16n8k16.row.col.f32.bf16.bf16.f32 "
        "{%0,%1,%2,%3}, {%4,%5,%6,%7}, {%8,%9}, {%0,%1,%2,%3};"
        : "+f"(c[0]), "+f"(c[1]), "+f"(c[2]), "+f"(c[3])
        : "r"(a[0]), "r"(a[1]), "r"(a[2]), "r"(a[3]), "r"(b[0]), "r"(b[1]));
}
__device__ __forceinline__ void bfsplit(float x, __nv_bfloat16& hi, __nv_bfloat16& lo) {
    hi = __float2bfloat16(x);
    lo = __float2bfloat16(x - __bfloat162float(hi));
}

// ---------------- prep kernels ---------------------------------------------
__global__ void k_split(const float* __restrict__ s) {      // xmm -> g_Amm
    const int i = blockIdx.x * 256 + threadIdx.x;
    if (i >= M_ROWS * DIM / 2) return;
    const float2 v = reinterpret_cast<const float2*>(s)[i];
    __nv_bfloat16 h0, l0, h1, l1;
    bfsplit(v.x, h0, l0); bfsplit(v.y, h1, l1);
    reinterpret_cast<__nv_bfloat162*>(g_Amm_hi)[i] = __halves2bfloat162(h0, h1);
    reinterpret_cast<__nv_bfloat162*>(g_Amm_lo)[i] = __halves2bfloat162(l0, l1);
}

__global__ void k_split_gather(const float* __restrict__ xv, const float* __restrict__ xa) {
    const int u = blockIdx.x * 256 + threadIdx.x;
    if (u >= M_ROWS * DIM / 2) return;
    const int row = u / (DIM / 2), c2 = u - row * (DIM / 2);
    const int b = row >> 8, t = row & 255;
    const float* src = (t < NV) ? xv + ((size_t)(b * NV + t)) * DIM
                                : xa + ((size_t)(b * NA + (t - NV))) * DIM;
    const float2 v = reinterpret_cast<const float2*>(src)[c2];
    __nv_bfloat16 h0, l0, h1, l1;
    bfsplit(v.x, h0, l0); bfsplit(v.y, h1, l1);
    reinterpret_cast<__nv_bfloat162*>(g_Asrc_hi)[u] = __halves2bfloat162(h0, h1);
    reinterpret_cast<__nv_bfloat162*>(g_Asrc_lo)[u] = __halves2bfloat162(l0, l1);
}

template <int WSEL>   // 0=Wq, 1=Wkv, 2=Wproj  : W [768][N] -> WT hi/lo [N][768]
__global__ void k_transpose_split(const float* __restrict__ W, int N) {
    __shared__ float t[32][33];
    const int n0 = blockIdx.x * 32, k0 = blockIdx.y * 32;
    const int tx = threadIdx.x & 31, ty = threadIdx.x >> 5;   // 32 x 8
#pragma unroll
    for (int i = 0; i < 4; i++)
        t[ty + 8 * i][tx] = W[(size_t)(k0 + ty + 8 * i) * N + n0 + tx];
    __syncthreads();
    __nv_bfloat16* Thi = (WSEL == 0) ? g_WqT_hi : (WSEL == 1) ? g_WkvT_hi : g_WpT_hi;
    __nv_bfloat16* Tlo = (WSEL == 0) ? g_WqT_lo : (WSEL == 1) ? g_WkvT_lo : g_WpT_lo;
#pragma unroll
    for (int i = 0; i < 4; i++) {
        const float x = t[tx][ty + 8 * i];
        __nv_bfloat16 h, l;
        bfsplit(x, h, l);
        const size_t o = (size_t)(n0 + ty + 8 * i) * DIM + k0 + tx;
        Thi[o] = h; Tlo[o] = l;
    }
}

// ---------------- projection GEMMs (mma.sync, bf16 hi/lo) ------------------
// CTA tile 128x128, BK=32, 8 warps (64x32 warp tiles). occupancy 2 CTA/SM.
#define TILE_B   8192               // one 128x32 bf16 tile, bytes
#define BUF_B    (4 * TILE_B)       // Ah, Al, Bh, Bl = 32 KB per stage
__device__ __forceinline__ uint32_t sw_off(int row, int c16) {
    return (uint32_t)(row * 64 + ((c16 ^ ((row >> 1) & 3)) << 4));
}

template <int MODE>   // 0: Q-proj, 1: KV-proj, 2: O-proj
__global__ __launch_bounds__(256, 2)
void tc_gemm(const float* __restrict__ bias, float* __restrict__ C)
{
    extern __shared__ char smem[];
    const uint32_t sb = smem_u32(smem);
    const int tid = threadIdx.x, wid = tid >> 5, lane = tid & 31;
    const int m0 = blockIdx.y * 128, n0 = blockIdx.x * 128;
    const int wm = wid & 1, wn = wid >> 1;          // warp tile (wm*64, wn*32)

    const __nv_bfloat16* Ahi = (MODE == 0) ? g_Amm_hi : (MODE == 1) ? g_Asrc_hi : g_AO_hi;
    const __nv_bfloat16* Alo = (MODE == 0) ? g_Amm_lo : (MODE == 1) ? g_Asrc_lo : g_AO_lo;
    const __nv_bfloat16* Bhi = (MODE == 0) ? g_WqT_hi : (MODE == 1) ? g_WkvT_hi : g_WpT_hi;
    const __nv_bfloat16* Blo = (MODE == 0) ? g_WqT_lo : (MODE == 1) ? g_WkvT_lo : g_WpT_lo;

    const char* gsrc[4] = {
        (const char*)(Ahi + (size_t)m0 * DIM), (const char*)(Alo + (size_t)m0 * DIM),
        (const char*)(Bhi + (size_t)n0 * DIM), (const char*)(Blo + (size_t)n0 * DIM) };

    const int ck0 = tid, ck1 = tid + 256;
    auto issue = [&](int it) {
        const int kb = it * 64;
        const uint32_t bufb = sb + (uint32_t)(it & 1) * BUF_B;
#pragma unroll
        for (int t = 0; t < 4; t++) {
            { const int row = ck0 >> 2, c16 = ck0 & 3;
              cp_async16(bufb + t * TILE_B + sw_off(row, c16),
                         gsrc[t] + (size_t)row * (DIM * 2) + kb + c16 * 16); }
            { const int row = ck1 >> 2, c16 = ck1 & 3;
              cp_async16(bufb + t * TILE_B + sw_off(row, c16),
                         gsrc[t] + (size_t)row * (DIM * 2) + kb + c16 * 16); }
        }
        cp_commit();
    };

    float acc[4][4][4];
#pragma unroll
    for (int i = 0; i < 4; i++)
#pragma unroll
        for (int j = 0; j < 4; j++)
#pragma unroll
            for (int r = 0; r < 4; r++) acc[i][j][r] = 0.f;

    const int matA = lane >> 3, wiA = lane & 7;
    const int a_moff = ((matA & 1) << 3) + wiA;
    const int a_ksel = matA >> 1;
    const int b_noff = ((matA >> 1) << 3) + wiA;
    const int b_ksel = matA & 1;

    issue(0);
    const int NITER = DIM / 32;                        // 24
    for (int it = 0; it < NITER; it++) {
        if (it + 1 < NITER) { issue(it + 1); cp_wait<1>(); }
        else                 cp_wait<0>();
        __syncthreads();
        const uint32_t bufb = sb + (uint32_t)(it & 1) * BUF_B;
        const uint32_t sAh = bufb, sAl = bufb + TILE_B;
        const uint32_t sBh = bufb + 2 * TILE_B, sBl = bufb + 3 * TILE_B;
#pragma unroll
        for (int kk = 0; kk < 2; kk++) {
            uint32_t ah[4][4], al[4][4], bh[2][4], bl[2][4];
#pragma unroll
            for (int mi = 0; mi < 4; mi++) {
                const int row = wm * 64 + mi * 16 + a_moff;
                const uint32_t o = sw_off(row, kk * 2 + a_ksel);
                ldmatrix_x4(ah[mi][0], ah[mi][1], ah[mi][2], ah[mi][3], sAh + o);
                ldmatrix_x4(al[mi][0], al[mi][1], al[mi][2], al[mi][3], sAl + o);
            }
#pragma unroll
            for (int ni = 0; ni < 2; ni++) {
                const int row = wn * 32 + ni * 16 + b_noff;
                const uint32_t o = sw_off(row, kk * 2 + b_ksel);
                ldmatrix_x4(bh[ni][0], bh[ni][1], bh[ni][2], bh[ni][3], sBh + o);
                ldmatrix_x4(bl[ni][0], bl[ni][1], bl[ni][2], bl[ni][3], sBl + o);
            }
#pragma unroll
            for (int mi = 0; mi < 4; mi++)
#pragma unroll
                for (int n8 = 0; n8 < 4; n8++) {
                    const int ni = n8 >> 1, p = (n8 & 1) << 1;
                    uint32_t bfh[2] = { bh[ni][p], bh[ni][p + 1] };
                    uint32_t bfl[2] = { bl[ni][p], bl[ni][p + 1] };
                    mma_bf16(acc[mi][n8], ah[mi], bfh);
                    mma_bf16(acc[mi][n8], ah[mi], bfl);
                    mma_bf16(acc[mi][n8], al[mi], bfh);
                }
        }
        __syncthreads();
    }

    const int gi = lane >> 2, qi = lane & 3;
#pragma unroll
    for (int mi = 0; mi < 4; mi++)
#pragma unroll
        for (int n8 = 0; n8 < 4; n8++)
#pragma unroll
            for (int half = 0; half < 2; half++) {
                const int r  = m0 + wm * 64 + mi * 16 + gi + half * 8;
                const int cg = n0 + wn * 32 + n8 * 8 + qi * 2;
                float2 v = make_float2(acc[mi][n8][2 * half], acc[mi][n8][2 * half + 1]);
                if (MODE == 0) {
                    v.x *= 0.125f; v.y *= 0.125f;          // fold 1/sqrt(hd), exact
                    const int b = r >> 8, q = r & 255, h = cg >> 6, d = cg & 63;
                    __nv_bfloat16 hx, lx, hy, ly;
                    bfsplit(v.x, hx, lx); bfsplit(v.y, hy, ly);
                    const size_t o = (((size_t)b * HEADS + h) * NMM + q) * HD + d;
                    *reinterpret_cast<__nv_bfloat162*>(&g_Qh[o]) = __halves2bfloat162(hx, hy);
                    *reinterpret_cast<__nv_bfloat162*>(&g_Ql[o]) = __halves2bfloat162(lx, ly);
                } else if (MODE == 1) {
                    const int b = r >> 8, t = r & 255;
                    __nv_bfloat16 hx, lx, hy, ly;
                    bfsplit(v.x, hx, lx); bfsplit(v.y, hy, ly);
                    if (cg < DIM) {
                        const int h = cg >> 6, d = cg & 63;
                        const size_t o = (((size_t)b * HEADS + h) * NKV + t) * HD + d;
                        *reinterpret_cast<__nv_bfloat162*>(&g_Kh[o]) = __halves2bfloat162(hx, hy);
                        *reinterpret_cast<__nv_bfloat162*>(&g_Kl[o]) = __halves2bfloat162(lx, ly);
                    } else {
                        const int c2 = cg - DIM, h = c2 >> 6, d = c2 & 63;
                        const size_t vb = ((size_t)b * HEADS + h) * HD;
                        g_VTh[(vb + d) * NKV + t] = hx; g_VTh[(vb + d + 1) * NKV + t] = hy;
                        g_VTl[(vb + d) * NKV + t] = lx; g_VTl[(vb + d + 1) * NKV + t] = ly;
                    }
                } else {
                    v.x += bias[cg]; v.y += bias[cg + 1];
                    *reinterpret_cast<float2*>(&C[(size_t)r * DIM + cg]) = v;
                }
            }
}

// ---------------- fused attention (unchanged from R8) ----------------------
#define FA_KB   0
#define FA_QB   65536
#define FA_VB   81920
#define FA_RED  147456
#define FA_SMEM (FA_RED + 2048)

__global__ __launch_bounds__(256, 1)
void fattn(float* __restrict__ attn)
{
    extern __shared__ char smem[];
    const uint32_t sb = smem_u32(smem);
    const int tid = threadIdx.x, wid = tid >> 5, lane = tid & 31;
    const int m0 = blockIdx.x * 64, bh = blockIdx.y;
    const int b = bh / HEADS, h = bh - b * HEADS;
    const int wm = wid & 1, wn = wid >> 1;            // S phase: 2(m) x 4(n)

    const int matA = lane >> 3, wiA = lane & 7;
    const int a_moff = ((matA & 1) << 3) + wiA;
    const int a_ksel = matA >> 1;
    const int b_noff = ((matA >> 1) << 3) + wiA;
    const int b_ksel = matA & 1;
    const int gi = lane >> 2, qi = lane & 3;

    const char* KH = (const char*)(g_Kh + (size_t)bh * NKV * HD);
    const char* KL = (const char*)(g_Kl + (size_t)bh * NKV * HD);
    const char* QH = (const char*)(g_Qh + ((size_t)bh * NMM + m0) * HD);
    const char* QL = (const char*)(g_Ql + ((size_t)bh * NMM + m0) * HD);
    const char* VH = (const char*)(g_VTh + (size_t)bh * HD * NKV);
    const char* VL = (const char*)(g_VTl + (size_t)bh * HD * NKV);

#pragma unroll
    for (int u = 0; u < 8; u++) {
        const int i = u * 256 + tid;
        const int t = i >> 3, c = (i >> 2) & 1, c16 = i & 3;
        cp_async16(sb + FA_KB + c * 16384 + sw_off(t, c16), KH + t * 128 + c * 64 + c16 * 16);
        cp_async16(sb + FA_KB + 32768 + c * 16384 + sw_off(t, c16), KL + t * 128 + c * 64 + c16 * 16);
    }
#pragma unroll
    for (int u = 0; u < 2; u++) {
        const int i = u * 256 + tid;
        const int r = i >> 3, c = (i >> 2) & 1, c16 = i & 3;
        cp_async16(sb + FA_QB + c * 4096 + sw_off(r, c16), QH + r * 128 + c * 64 + c16 * 16);
        cp_async16(sb + FA_QB + 8192 + c * 4096 + sw_off(r, c16), QL + r * 128 + c * 64 + c16 * 16);
    }
    cp_commit();
#pragma unroll
    for (int u = 0; u < 8; u++) {
        const int i = u * 256 + tid;
        const int d = i >> 5, ch = (i >> 2) & 7, c16 = i & 3;
        cp_async16(sb + FA_VB + ch * 4096 + sw_off(d, c16), VH + d * 512 + ch * 64 + c16 * 16);
        cp_async16(sb + FA_VB + 32768 + ch * 4096 + sw_off(d, c16), VL + d * 512 + ch * 64 + c16 * 16);
    }
    cp_commit();
    cp_wait<1>();
    __syncthreads();

    float acc[2][8][4];
#pragma unroll
    for (int i = 0; i < 2; i++)
#pragma unroll
        for (int j = 0; j < 8; j++)
#pragma unroll
            for (int r = 0; r < 4; r++) acc[i][j][r] = 0.f;

#pragma unroll
    for (int ch = 0; ch < 2; ch++)
#pragma unroll
        for (int kk = 0; kk < 2; kk++) {
            uint32_t ah[2][4], al[2][4], bhv[4][4], blv[4][4];
#pragma unroll
            for (int mi = 0; mi < 2; mi++) {
                const int row = wm * 32 + mi * 16 + a_moff;
                const uint32_t o = FA_QB + ch * 4096 + sw_off(row, kk * 2 + a_ksel);
                ldmatrix_x4(ah[mi][0], ah[mi][1], ah[mi][2], ah[mi][3], sb + o);
                ldmatrix_x4(al[mi][0], al[mi][1], al[mi][2], al[mi][3], sb + o + 8192);
            }
#pragma unroll
            for (int ni = 0; ni < 4; ni++) {
                const int row = wn * 64 + ni * 16 + b_noff;
                const uint32_t o = FA_KB + ch * 16384 + sw_off(row, kk * 2 + b_ksel);
                ldmatrix_x4(bhv[ni][0], bhv[ni][1], bhv[ni][2], bhv[ni][3], sb + o);
                ldmatrix_x4(blv[ni][0], blv[ni][1], blv[ni][2], blv[ni][3], sb + o + 32768);
            }
#pragma unroll
            for (int mi = 0; mi < 2; mi++)
#pragma unroll
                for (int n8 = 0; n8 < 8; n8++) {
                    const int ni = n8 >> 1, p = (n8 & 1) << 1;
                    uint32_t bfh[2] = { bhv[ni][p], bhv[ni][p + 1] };
                    uint32_t bfl[2] = { blv[ni][p], blv[ni][p + 1] };
                    mma_bf16(acc[mi][n8], ah[mi], bfh);
                    mma_bf16(acc[mi][n8], ah[mi], bfl);
                    mma_bf16(acc[mi][n8], al[mi], bfh);
                }
        }
    __syncthreads();

    float* redm = (float*)(smem + FA_RED);
    float* reds = (float*)(smem + FA_RED + 1024);
    float inv[2][2];
#pragma unroll
    for (int mi = 0; mi < 2; mi++)
#pragma unroll
        for (int hf = 0; hf < 2; hf++) {
            float m = -INFINITY;
#pragma unroll
            for (int n8 = 0; n8 < 8; n8++)
                m = fmaxf(m, fmaxf(acc[mi][n8][2 * hf], acc[mi][n8][2 * hf + 1]));
            m = fmaxf(m, __shfl_xor_sync(0xFFFFFFFFu, m, 1));
            m = fmaxf(m, __shfl_xor_sync(0xFFFFFFFFu, m, 2));
            if (qi == 0) redm[wn * 64 + wm * 32 + mi * 16 + gi + hf * 8] = m;
        }
    __syncthreads();
#pragma unroll
    for (int mi = 0; mi < 2; mi++)
#pragma unroll
        for (int hf = 0; hf < 2; hf++) {
            const int rl = wm * 32 + mi * 16 + gi + hf * 8;
            float m = fmaxf(fmaxf(redm[rl], redm[64 + rl]),
                            fmaxf(redm[128 + rl], redm[192 + rl]));
            float s = 0.f;
#pragma unroll
            for (int n8 = 0; n8 < 8; n8++) {
                float e0 = __expf(acc[mi][n8][2 * hf] - m);
                float e1 = __expf(acc[mi][n8][2 * hf + 1] - m);
                acc[mi][n8][2 * hf] = e0; acc[mi][n8][2 * hf + 1] = e1;
                s += e0 + e1;
            }
            s += __shfl_xor_sync(0xFFFFFFFFu, s, 1);
            s += __shfl_xor_sync(0xFFFFFFFFu, s, 2);
            if (qi == 0) reds[wn * 64 + rl] = s;
        }
    __syncthreads();
#pragma unroll
    for (int mi = 0; mi < 2; mi++)
#pragma unroll
        for (int hf = 0; hf < 2; hf++) {
            const int rl = wm * 32 + mi * 16 + gi + hf * 8;
            inv[mi][hf] = 1.0f / (reds[rl] + reds[64 + rl] + reds[128 + rl] + reds[192 + rl]);
        }

    float* outp = attn + ((size_t)bh * NMM + m0) * NKV;
#pragma unroll
    for (int mi = 0; mi < 2; mi++)
#pragma unroll
        for (int n8 = 0; n8 < 8; n8++)
#pragma unroll
            for (int hf = 0; hf < 2; hf++) {
                const int rl = wm * 32 + mi * 16 + gi + hf * 8;
                const int col = wn * 64 + n8 * 8 + qi * 2;
                const float px = acc[mi][n8][2 * hf] * inv[mi][hf];
                const float py = acc[mi][n8][2 * hf + 1] * inv[mi][hf];
                *reinterpret_cast<float2*>(&outp[(size_t)rl * NKV + col]) = make_float2(px, py);
                __nv_bfloat16 hx, lx, hy, ly;
                bfsplit(px, hx, lx); bfsplit(py, hy, ly);
                const int cc = col & 31;
                const uint32_t po = (uint32_t)((col >> 5) * 4096) + sw_off(rl, cc >> 3) + (cc & 7) * 2;
                __nv_bfloat162 hp = __halves2bfloat162(hx, hy);
                __nv_bfloat162 lp = __halves2bfloat162(lx, ly);
                *reinterpret_cast<uint32_t*>(smem + FA_KB + po) = *reinterpret_cast<uint32_t*>(&hp);
                *reinterpret_cast<uint32_t*>(smem + FA_KB + 32768 + po) = *reinterpret_cast<uint32_t*>(&lp);
            }
    cp_wait<0>();
    __syncthreads();

    const int om = wid & 3, on = wid >> 2;
    float oacc[4][4];
#pragma unroll
    for (int j = 0; j < 4; j++)
#pragma unroll
        for (int r = 0; r < 4; r++) oacc[j][r] = 0.f;

#pragma unroll
    for (int ch = 0; ch < 8; ch++)
#pragma unroll
        for (int kk = 0; kk < 2; kk++) {
            uint32_t pa[4], pl[4], vbh[2][4], vbl[2][4];
            {
                const int row = om * 16 + a_moff;
                const uint32_t o = FA_KB + ch * 4096 + sw_off(row, kk * 2 + a_ksel);
                ldmatrix_x4(pa[0], pa[1], pa[2], pa[3], sb + o);
                ldmatrix_x4(pl[0], pl[1], pl[2], pl[3], sb + o + 32768);
            }
#pragma unroll
            for (int ni = 0; ni < 2; ni++) {
                const int row = on * 32 + ni * 16 + b_noff;
                const uint32_t o = FA_VB + ch * 4096 + sw_off(row, kk * 2 + b_ksel);
                ldmatrix_x4(vbh[ni][0], vbh[ni][1], vbh[ni][2], vbh[ni][3], sb + o);
                ldmatrix_x4(vbl[ni][0], vbl[ni][1], vbl[ni][2], vbl[ni][3], sb + o + 32768);
            }
#pragma unroll
            for (int n8 = 0; n8 < 4; n8++) {
                const int ni = n8 >> 1, p = (n8 & 1) << 1;
                uint32_t bfh[2] = { vbh[ni][p], vbh[ni][p + 1] };
                uint32_t bfl[2] = { vbl[ni][p], vbl[ni][p + 1] };
                mma_bf16(oacc[n8], pa, bfh);
                mma_bf16(oacc[n8], pa, bfl);
                mma_bf16(oacc[n8], pl, bfh);
            }
        }

#pragma unroll
    for (int n8 = 0; n8 < 4; n8++)
#pragma unroll
        for (int hf = 0; hf < 2; hf++) {
            const int q = m0 + om * 16 + gi + hf * 8;
            const int d = on * 32 + n8 * 8 + qi * 2;
            __nv_bfloat16 hx, lx, hy, ly;
            bfsplit(oacc[n8][2 * hf], hx, lx); bfsplit(oacc[n8][2 * hf + 1], hy, ly);
            const size_t o = ((size_t)b * NMM + q) * DIM + h * HD + d;
            *reinterpret_cast<__nv_bfloat162*>(&g_AO_hi[o]) = __halves2bfloat162(hx, hy);
            *reinterpret_cast<__nv_bfloat162*>(&g_AO_lo[o]) = __halves2bfloat162(lx, ly);
        }
}

// ---------------------------------------------------------------------------
extern "C" void kernel_launch(void* const* d_in, const int* in_sizes, int n_in,
                              void* d_out, int out_size)
{
    const float* xmm   = (const float*)d_in[0];
    const float* xv    = (const float*)d_in[1];
    const float* xa    = (const float*)d_in[2];
    const float* Wq    = (const float*)d_in[3];
    const float* Wkv   = (const float*)d_in[4];
    const float* Wproj = (const float*)d_in[5];
    const float* bproj = (const float*)d_in[6];

    float* out  = (float*)d_out;
    float* attn = out + (size_t)BS * NMM * DIM;

    const int GEMM_SMEM = 2 * BUF_B;   // 64 KB (2 CTAs/SM = 128 KB)
    cudaFuncSetAttribute(tc_gemm<0>, cudaFuncAttributeMaxDynamicSharedMemorySize, GEMM_SMEM);
    cudaFuncSetAttribute(tc_gemm<1>, cudaFuncAttributeMaxDynamicSharedMemorySize, GEMM_SMEM);
    cudaFuncSetAttribute(tc_gemm<2>, cudaFuncAttributeMaxDynamicSharedMemorySize, GEMM_SMEM);
    cudaFuncSetAttribute(fattn,      cudaFuncAttributeMaxDynamicSharedMemorySize, FA_SMEM);

    const int nsplit = M_ROWS * DIM / 2;
    // Launch order keeps tc_gemm<1> at index 3 (ncu's capture slot).
    k_split<<<(nsplit + 255) / 256, 256>>>(xmm);                               // 0
    k_split_gather<<<(nsplit + 255) / 256, 256>>>(xv, xa);                     // 1
    k_transpose_split<1><<<dim3(2 * DIM / 32, DIM / 32), 256>>>(Wkv, 2 * DIM); // 2
    tc_gemm<1><<<dim3(2 * DIM / 128, M_ROWS / 128), 256, GEMM_SMEM>>>(nullptr, nullptr); // 3
    k_transpose_split<0><<<dim3(DIM / 32, DIM / 32), 256>>>(Wq, DIM);          // 4
    tc_gemm<0><<<dim3(DIM / 128, M_ROWS / 128), 256, GEMM_SMEM>>>(nullptr, nullptr);     // 5
    fattn<<<dim3(NMM / 64, BS * HEADS), 256, FA_SMEM>>>(attn);                 // 6
    k_transpose_split<2><<<dim3(DIM / 32, DIM / 32), 256>>>(Wproj, DIM);       // 7
    tc_gemm<2><<<dim3(DIM / 128, M_ROWS / 128), 256, GEMM_SMEM>>>(bproj, out); // 8
}